// round 17
// baseline (speedup 1.0000x reference)
#include <cuda_runtime.h>
#include <cstddef>

// Problem constants
#define SQ   512      // sequence length S
#define ED   512      // embedding dim E
#define HD   512      // hidden dim H
#define G4   2048     // 4*H gates
#define BSEL 63       // only batch sample 63 reaches the output
#define NVOC 32000

#define NCTA 64       // scan CTAs; each owns 8 h elements
#define TPB  512      // 16 warps

// g_hist layout: [t][cta][32-word padded block]; CTA c's 8 published words
// live at the START of their own 128B line -> no poll/publish line sharing.
#define HSTRIDE 2048                  // 64 CTAs * 32 words per step
__device__ float g_hist[SQ * HSTRIDE];   // 4 MB
__device__ float g_xg[SQ * G4];          // xg TRANSPOSED: [t][element][gate], 4 MB
__device__ int   g_tok[SQ];              // batch-63 tokens, dtype-normalized

__device__ __forceinline__ int hist_idx(int e) {   // element -> padded offset
    return ((e >> 3) << 5) + (e & 7);
}

// ---------------------------------------------------------------------------
// Kernel 0a: zero the history buffer so graph replays are deterministic.
// ---------------------------------------------------------------------------
__global__ void zero_hist_kernel() {
    int idx = blockIdx.x * blockDim.x + threadIdx.x;
    int stride = gridDim.x * blockDim.x;
    for (int i = idx; i < SQ * HSTRIDE; i += stride) g_hist[i] = 0.f;
}

// ---------------------------------------------------------------------------
// Kernel 0b: normalize token dtype (int32 vs int64) and extract batch 63.
// ---------------------------------------------------------------------------
__global__ void __launch_bounds__(SQ) token_prep_kernel(const int* __restrict__ raw) {
    __shared__ int any_nz;
    const int tid = threadIdx.x;            // 0..511
    if (tid == 0) any_nz = 0;
    __syncthreads();
    if (tid < 256 && raw[2 * tid + 1] != 0) atomicExch(&any_nz, 1);
    __syncthreads();
    const bool is64 = (any_nz == 0);
    const long long idx = (long long)BSEL * SQ + tid;
    int tok = is64 ? raw[2 * idx] : raw[idx];
    tok = min(max(tok, 0), NVOC - 1);       // never IMA, even on dtype surprise
    g_tok[tid] = tok;
}

// ---------------------------------------------------------------------------
// Kernel 1: xg GEMM, output TRANSPOSED to [t][element][gate].
// ---------------------------------------------------------------------------
#define BM 64
#define BN 64
#define BK 16

__global__ void __launch_bounds__(256) xg_gemm_kernel(
    const float* __restrict__ emb,
    const float* __restrict__ Wih,
    const float* __restrict__ bih,
    const float* __restrict__ bhh)
{
    __shared__ float As[BK][BM];
    __shared__ float Bs[BK][BN];
    __shared__ int   toks[BM];

    const int bs = blockIdx.x * BM;   // s base
    const int bg = blockIdx.y * BN;   // g base
    const int tid = threadIdx.x;

    if (tid < BM) toks[tid] = g_tok[bs + tid];
    __syncthreads();

    const int tm = (tid >> 4) << 2;   // 0,4,...,60
    const int tn = (tid & 15) << 2;   // 0,4,...,60

    float acc[4][4];
    #pragma unroll
    for (int i = 0; i < 4; i++)
        #pragma unroll
        for (int j = 0; j < 4; j++) acc[i][j] = 0.f;

    for (int k0 = 0; k0 < ED; k0 += BK) {
        #pragma unroll
        for (int i = tid; i < BM * BK; i += 256) {
            int m = i >> 4, k = i & 15;
            As[k][m] = emb[(size_t)toks[m] * ED + k0 + k];
        }
        #pragma unroll
        for (int i = tid; i < BN * BK; i += 256) {
            int n = i >> 4, k = i & 15;
            Bs[k][n] = Wih[(size_t)(bg + n) * ED + k0 + k];
        }
        __syncthreads();
        #pragma unroll
        for (int k = 0; k < BK; k++) {
            float4 a = *(const float4*)&As[k][tm];
            float4 b = *(const float4*)&Bs[k][tn];
            float av[4] = {a.x, a.y, a.z, a.w};
            float bv[4] = {b.x, b.y, b.z, b.w};
            #pragma unroll
            for (int i = 0; i < 4; i++)
                #pragma unroll
                for (int j = 0; j < 4; j++)
                    acc[i][j] = fmaf(av[i], bv[j], acc[i][j]);
        }
        __syncthreads();
    }

    #pragma unroll
    for (int i = 0; i < 4; i++) {
        int s = bs + tm + i;
        #pragma unroll
        for (int j = 0; j < 4; j++) {
            int g = bg + tn + j;
            int e = g & (HD - 1), q = g >> 9;
            g_xg[(size_t)s * G4 + (e << 2) + q] = acc[i][j] + bih[g] + bhh[g];
        }
    }
}

// ---------------------------------------------------------------------------
// Kernel 2: persistent LSTM scan, batch element 63 only.  (R16 base.)
// 64 CTAs x 512 threads (16 warps). CTA c owns h elements [8c, 8c+8).
// Warp w computes 2 of the CTA's 32 gate dots; warp0 lanes 0-7 do hw-tanh
// activations and publish h+2 for all 8 elements in ONE coalesced 32B store.
// R17 deltas: (1) g_hist padded so each producer CTA's block owns a full
// 128B line — polls no longer saturate the publish line's LTS slice;
// (2) 6-shfl dual reduce; (3) gexch stored [e][q] so warp0 reads LDS.128.
// ---------------------------------------------------------------------------
__device__ __forceinline__ float tanh_hw(float x) {
    float y;
    asm("tanh.approx.f32 %0, %1;" : "=f"(y) : "f"(x));
    return y;
}
__device__ __forceinline__ float sigmoid_hw(float x) {
    return fmaf(0.5f, tanh_hw(0.5f * x), 0.5f);
}

__global__ void __launch_bounds__(TPB, 1) lstm_scan_kernel(
    const float* __restrict__ h0,
    const float* __restrict__ c0,
    const float* __restrict__ Whh)
{
    __shared__ float h_sm[2][HD];       // parity double-buffered h+2 (4 KB)
    __shared__ float gexch[32];         // gate pre-activations, [e][q] layout

    const int cta = blockIdx.x;         // 0..63
    const int tid = threadIdx.x;
    const int w = tid >> 5;             // warp 0..15
    const int l = tid & 31;

    // Warp w owns dots d0=2w, d1=2w+1; d = q*8+e (q=gate 0..3, e=local elem 0..7)
    const int d0 = 2 * w, d1 = 2 * w + 1;
    const int r0 = ((d0 >> 3) << 9) + (cta << 3) + (d0 & 7);   // W_hh row for d0
    const int r1 = ((d1 >> 3) << 9) + (cta << 3) + (d1 & 7);
    float wt0[16], wt1[16];
    #pragma unroll
    for (int a = 0; a < 4; a++) {
        float4 v = *(const float4*)&Whh[((size_t)r0 << 9) + (a << 7) + (l << 2)];
        wt0[a * 4 + 0] = v.x; wt0[a * 4 + 1] = v.y;
        wt0[a * 4 + 2] = v.z; wt0[a * 4 + 3] = v.w;
        float4 u = *(const float4*)&Whh[((size_t)r1 << 9) + (a << 7) + (l << 2)];
        wt1[a * 4 + 0] = u.x; wt1[a * 4 + 1] = u.y;
        wt1[a * 4 + 2] = u.z; wt1[a * 4 + 3] = u.w;
    }

    // Row sums (x2) for the offset-fold: dot(W, h+2) - 2*sum(W) = dot(W, h).
    float rs0 = 0.f, rs1 = 0.f;
    #pragma unroll
    for (int i = 0; i < 16; i++) { rs0 += wt0[i]; rs1 += wt1[i]; }
    #pragma unroll
    for (int off = 16; off; off >>= 1) {
        rs0 += __shfl_xor_sync(0xffffffffu, rs0, off);
        rs1 += __shfl_xor_sync(0xffffffffu, rs1, off);
    }
    rs0 *= 2.f; rs1 *= 2.f;

    // gexch [e][q] addresses for this warp's two dots
    const int ga0 = (((d0 & 7)) << 2) + (d0 >> 3);
    const int ga1 = (((d1 & 7)) << 2) + (d1 >> 3);
    // xg addresses (transposed [element][gate]) for lane-0 seeds
    const int xga_off = (((cta << 3) + (d0 & 7)) << 2) + (d0 >> 3);
    const int xgb_off = (((cta << 3) + (d1 & 7)) << 2) + (d1 >> 3);

    float creg = 0.f;
    if (w == 0 && l < 8) creg = c0[(size_t)BSEL * HD + (cta << 3) + l];

    // Seed h_sm[0] with h0[0, 63, :] + 2 (offset domain)
    h_sm[0][tid] = h0[(size_t)BSEL * HD + tid] + 2.0f;
    __syncthreads();

    // Poll address precompute: warp w covers elements [32w, 32w+32)
    const int e_poll = (w << 5) + l;
    const int hoff_poll = hist_idx(e_poll);

    for (int t = 0; t < SQ; t++) {
        // Lane 0: prefetch this step's two xg biases before the poll (overlapped).
        float xga = 0.f, xgb = 0.f;
        if (l == 0) {
            xga = g_xg[((size_t)t << 11) + xga_off];
            xgb = g_xg[((size_t)t << 11) + xgb_off];
        }

        if (t > 0) {
            // Poll h(t-1): 1 word/lane, 4 padded lines per warp (1 sector each).
            const float* p = g_hist + ((t - 1) << 11) + hoff_poll;
            unsigned a;
            for (;;) {
                asm volatile("ld.volatile.global.u32 %0, [%1];" : "=r"(a) : "l"(p));
                if (__all_sync(0xffffffffu, a != 0u)) break;
            }
            h_sm[t & 1][e_poll] = __uint_as_float(a);   // raw h+2, no debias
        }
        __syncthreads();

        // Two 512-length dots (h+2 from smem, W from registers).
        const float* hb = h_sm[t & 1];
        float hreg[16];
        #pragma unroll
        for (int a = 0; a < 4; a++) {
            float4 v = *(const float4*)&hb[(a << 7) + (l << 2)];
            hreg[a * 4 + 0] = v.x; hreg[a * 4 + 1] = v.y;
            hreg[a * 4 + 2] = v.z; hreg[a * 4 + 3] = v.w;
        }
        float s0 = (l == 0) ? (xga - rs0) : 0.f;   // bias + offset-fold, once
        float s1 = (l == 0) ? (xgb - rs1) : 0.f;
        #pragma unroll
        for (int i = 0; i < 16; i++) {
            s0 = fmaf(wt0[i], hreg[i], s0);
            s1 = fmaf(wt1[i], hreg[i], s1);
        }
        // 6-shfl dual reduce: fold both by 16, select halves, fold 8/4/2/1.
        s0 += __shfl_xor_sync(0xffffffffu, s0, 16);
        s1 += __shfl_xor_sync(0xffffffffu, s1, 16);
        float v = (l & 16) ? s1 : s0;
        v += __shfl_xor_sync(0xffffffffu, v, 8);
        v += __shfl_xor_sync(0xffffffffu, v, 4);
        v += __shfl_xor_sync(0xffffffffu, v, 2);
        v += __shfl_xor_sync(0xffffffffu, v, 1);
        if (l == 0)  gexch[ga0] = v;    // lane 0:  full s0
        if (l == 16) gexch[ga1] = v;    // lane 16: full s1
        __syncthreads();

        // Warp0 lanes 0-7: one LDS.128 of this element's 4 gates, hw-tanh
        // activations, ONE coalesced 32B publish into the CTA's private line.
        if (w == 0 && l < 8) {
            float4 g4 = *(const float4*)&gexch[l << 2];   // {i,f,g,o}
            float iv = sigmoid_hw(g4.x);
            float fv = sigmoid_hw(g4.y);
            float gv = tanh_hw(g4.z);
            float ov = sigmoid_hw(g4.w);
            creg = fv * creg + iv * gv;
            float hv = ov * tanh_hw(creg);
            float pub = hv + 2.0f;          // in (1,3): never zero bits
            float* dst = g_hist + (t << 11) + (cta << 5) + l;
            asm volatile("st.relaxed.gpu.global.f32 [%0], %1;"
                         :: "l"(dst), "f"(pub) : "memory");
        }
        // h_sm is parity double-buffered; the two barriers above bound skew.
    }
}

// ---------------------------------------------------------------------------
// Kernel 3: out[s,t] = (hist[s,:]-2) . W_lin[t,:] + b_lin[t]   (1024 outputs)
// ---------------------------------------------------------------------------
__global__ void __launch_bounds__(256) final_linear_kernel(
    const float* __restrict__ Wlin,
    const float* __restrict__ blin,
    float* __restrict__ out)
{
    const int w = threadIdx.x >> 5, l = threadIdx.x & 31;
    const int wi = blockIdx.x * 8 + w;     // 0..1023
    const int s = wi >> 1, tt = wi & 1;
    float acc = 0.f;
    #pragma unroll
    for (int e = l; e < HD; e += 32) {
        float hv = g_hist[(size_t)s * HSTRIDE + ((e >> 3) << 5) + (e & 7)] - 2.0f;
        acc = fmaf(hv, Wlin[(size_t)tt * HD + e], acc);
    }
    #pragma unroll
    for (int off = 16; off; off >>= 1) acc += __shfl_xor_sync(0xffffffffu, acc, off);
    if (l == 0) out[s * 2 + tt] = acc + blin[tt];
}

// ---------------------------------------------------------------------------
extern "C" void kernel_launch(void* const* d_in, const int* in_sizes, int n_in,
                              void* d_out, int out_size)
{
    const int*   sent = (const int*)d_in[0];            // (64,512) int32/int64 words
    const float* h0   = (const float*)d_in[1];          // (1,64,512)
    const float* c0   = (const float*)d_in[2];          // (1,64,512)
    const float* emb  = (const float*)d_in[3];          // (32000,512)
    const float* Wih  = (const float*)d_in[4];          // (2048,512)
    const float* Whh  = (const float*)d_in[5];          // (2048,512)
    const float* bih  = (const float*)d_in[6];          // (2048,)
    const float* bhh  = (const float*)d_in[7];          // (2048,)
    const float* Wlin = (const float*)d_in[8];          // (2,512)
    const float* blin = (const float*)d_in[9];          // (2,)
    float* out = (float*)d_out;                         // (512,2)

    zero_hist_kernel<<<512, 256>>>();
    token_prep_kernel<<<1, SQ>>>(sent);
    xg_gemm_kernel<<<dim3(SQ / BM, G4 / BN), 256>>>(emb, Wih, bih, bhh);
    lstm_scan_kernel<<<NCTA, TPB>>>(h0, c0, Whh);
    final_linear_kernel<<<128, 256>>>(Wlin, blin, out);
}